// round 7
// baseline (speedup 1.0000x reference)
#include <cuda_runtime.h>
#include <cuda_fp16.h>
#include <cstdint>

#define BB   4
#define CC   512
#define NSEQ 4096
#define DQK  64
#define LOG2E 1.4426950408889634f

// ---------------- scratch (static device globals: allocation-free) ----------
__device__ __half g_qh[BB * NSEQ * DQK];            // [b][i][d] hi
__device__ __half g_ql[BB * NSEQ * DQK];            // [b][i][d] lo
__device__ __half g_kh[BB * NSEQ * DQK];            // [b][j][d] hi
__device__ __half g_kl[BB * NSEQ * DQK];            // [b][j][d] lo
__device__ __half g_v [(size_t)BB * CC * NSEQ];     // [b][c][j] single fp16

// ---------------- fast exp2 --------------------------------------------------
__device__ __forceinline__ float exp2_fast(float y) {
    y = fmaxf(y, -120.0f);
    float t = y + 12582912.0f;
    float n = t - 12582912.0f;
    float f = y - n;
    float p = 1.3333558e-3f;
    p = fmaf(p, f, 9.6181291e-3f);
    p = fmaf(p, f, 5.5504109e-2f);
    p = fmaf(p, f, 2.4022651e-1f);
    p = fmaf(p, f, 6.9314718e-1f);
    p = fmaf(p, f, 1.0f);
    int ni = (int)n;
    return __int_as_float(__float_as_int(p) + (ni << 23));
}

__device__ __forceinline__ uint32_t smem_u32(const void* p) {
    uint32_t a;
    asm("{ .reg .u64 t; cvta.to.shared.u64 t, %1; cvt.u32.u64 %0, t; }" : "=r"(a) : "l"(p));
    return a;
}
__device__ __forceinline__ uint32_t pack_h2(float a, float b) {
    __half2 h = __floats2half2_rn(a, b);
    return *(uint32_t*)&h;
}
__device__ __forceinline__ void mma_f16(float* c, const uint32_t* a, uint32_t b0, uint32_t b1) {
    asm volatile("mma.sync.aligned.m16n8k16.row.col.f32.f16.f16.f32 "
        "{%0,%1,%2,%3}, {%4,%5,%6,%7}, {%8,%9}, {%0,%1,%2,%3};"
        : "+f"(c[0]), "+f"(c[1]), "+f"(c[2]), "+f"(c[3])
        : "r"(a[0]), "r"(a[1]), "r"(a[2]), "r"(a[3]), "r"(b0), "r"(b1));
}
__device__ __forceinline__ void ldsm4(uint32_t* r, uint32_t a) {
    asm volatile("ldmatrix.sync.aligned.m8n8.x4.shared.b16 {%0,%1,%2,%3}, [%4];"
        : "=r"(r[0]), "=r"(r[1]), "=r"(r[2]), "=r"(r[3]) : "r"(a));
}
__device__ __forceinline__ void cp16(uint32_t dst, const void* src) {
    asm volatile("cp.async.cg.shared.global [%0], [%1], 16;" :: "r"(dst), "l"(src));
}
#define CP_COMMIT() asm volatile("cp.async.commit_group;" ::: "memory")
#define CP_WAIT1()  asm volatile("cp.async.wait_group 1;" ::: "memory")

__device__ __forceinline__ float2 lds64(uint32_t a) {
    float2 v; asm volatile("ld.shared.v2.f32 {%0,%1}, [%2];" : "=f"(v.x), "=f"(v.y) : "r"(a)); return v;
}
__device__ __forceinline__ void sts64(uint32_t a, float x, float y) {
    asm volatile("st.shared.v2.f32 [%0], {%1,%2};" :: "r"(a), "f"(x), "f"(y) : "memory");
}
__device__ __forceinline__ float lds32f(uint32_t a) {
    float v; asm volatile("ld.shared.f32 %0, [%1];" : "=f"(v) : "r"(a)); return v;
}
__device__ __forceinline__ void sts32f(uint32_t a, float v) {
    asm volatile("st.shared.f32 [%0], %1;" :: "r"(a), "f"(v) : "memory");
}

// ---------------- pass 1: QKV projection (SIMT fp32) ------------------------
__global__ __launch_bounds__(256) void proj_kernel(
    const float* __restrict__ x,
    const float* __restrict__ wq, const float* __restrict__ bq,
    const float* __restrict__ wk, const float* __restrict__ bk,
    const float* __restrict__ wv, const float* __restrict__ bv)
{
    __shared__ float ws[16][68];
    __shared__ float xs[16][64];

    const int b  = blockIdx.z;
    const int o0 = blockIdx.y * 64;
    const int n0 = blockIdx.x * 64;
    const int t  = threadIdx.x;
    const int tx = t & 15;
    const int ty = t >> 4;
    const float* xb = x + (size_t)b * CC * NSEQ;

    float acc[4][4];
#pragma unroll
    for (int i = 0; i < 4; i++)
#pragma unroll
        for (int j = 0; j < 4; j++) acc[i][j] = 0.f;

    const int wo  = t >> 2;
    const int wc4 = (t & 3) * 4;
    const int oo  = o0 + wo;
    const float* wrow;
    if (oo < 64)        wrow = wq + (size_t)oo * CC;
    else if (oo < 128)  wrow = wk + (size_t)(oo - 64) * CC;
    else                wrow = wv + (size_t)(oo - 128) * CC;

    const int xc  = t >> 4;
    const int xn4 = (t & 15) * 4;

    for (int c0 = 0; c0 < CC; c0 += 16) {
        float4 w4 = *(const float4*)(wrow + c0 + wc4);
        float4 x4 = *(const float4*)(xb + (size_t)(c0 + xc) * NSEQ + n0 + xn4);
        __syncthreads();
        ws[wc4 + 0][wo] = w4.x; ws[wc4 + 1][wo] = w4.y;
        ws[wc4 + 2][wo] = w4.z; ws[wc4 + 3][wo] = w4.w;
        *(float4*)&xs[xc][xn4] = x4;
        __syncthreads();
#pragma unroll
        for (int c = 0; c < 16; c++) {
            float4 a4 = *(const float4*)&ws[c][4 * ty];
            float4 b4 = *(const float4*)&xs[c][4 * tx];
            float a[4] = {a4.x, a4.y, a4.z, a4.w};
            float bv2[4] = {b4.x, b4.y, b4.z, b4.w};
#pragma unroll
            for (int i = 0; i < 4; i++)
#pragma unroll
                for (int j = 0; j < 4; j++)
                    acc[i][j] = fmaf(a[i], bv2[j], acc[i][j]);
        }
    }

    const int n = n0 + 4 * tx;
#pragma unroll
    for (int mi = 0; mi < 4; mi++) {
        int o = o0 + 4 * ty + mi;
        if (o < 128) {
            int d = o & 63;
            float bias = (o < 64) ? bq[d] : bk[d];
            __half* dh = ((o < 64) ? g_qh : g_kh) + ((size_t)b * NSEQ + n) * DQK + d;
            __half* dl = ((o < 64) ? g_ql : g_kl) + ((size_t)b * NSEQ + n) * DQK + d;
            float vs[4] = {acc[mi][0] + bias, acc[mi][1] + bias,
                           acc[mi][2] + bias, acc[mi][3] + bias};
#pragma unroll
            for (int j = 0; j < 4; j++) {
                __half h = __float2half_rn(vs[j]);
                __half l = __float2half_rn(vs[j] - __half2float(h));
                dh[(size_t)j * DQK] = h;
                dl[(size_t)j * DQK] = l;
            }
        } else {
            int c = o - 128;
            float bias = bv[c];
            size_t off = ((size_t)(b * CC + c)) * NSEQ + n;
            uint2 w2;
            w2.x = pack_h2(acc[mi][0] + bias, acc[mi][1] + bias);
            w2.y = pack_h2(acc[mi][2] + bias, acc[mi][3] + bias);
            *(uint2*)((char*)g_v + off * 2) = w2;
        }
    }
}

// ---------------- pass 2: two-phase HMMA flash attention ---------------------
// 512 threads, 16 warps. CTA: 128 i x 256 c, j in 64-chunks.
// Phase A: warp (ia=w&7, jh=w>>3): S[16i x 32j] -> SMEM (fp32) + row chunk-max.
// Phase B: warp (cb=w&3, ib=w>>2): softmax+pack from SMEM S, GEMM2 32i x 64c.
#define KROW   144
#define SROW   72            /* floats per S row */
#define S_Q    0             /* Q hi/lo: 2 x 18432 */
#define S_S    36864         /* S tile: 128*72*4 = 36864 */
#define S_CM   73728         /* chunk max: 2*128*4 = 1024 */
#define S_BUF  74752
#define SK_H   0
#define SK_L   9216
#define SV     18432
#define TILE_BYTES 55296
#define N_CHUNK (NSEQ / 64)
#define STG_ROW 132
#define OUT_SMEM_BYTES (S_BUF + 2 * TILE_BYTES)   /* 185344 */

__device__ __forceinline__ void issue_tiles(uint32_t tb, int b, int j0, int c0, int t)
{
#pragma unroll
    for (int r = 0; r < 2; r++) {           // K hi+lo: 1024 16B chunks
        int idx = t + r * 512;
        int arr = idx >> 9;
        int row = (idx >> 3) & 63;
        int col = idx & 7;
        const __half* src = (arr ? g_kl : g_kh) + ((size_t)b * NSEQ + j0 + row) * DQK + col * 8;
        cp16(tb + SK_H + arr * 9216 + row * KROW + col * 16, src);
    }
#pragma unroll
    for (int r = 0; r < 4; r++) {           // V: 2048 16B chunks (256 c rows)
        int idx = t + r * 512;
        int row = (idx >> 3) & 255;
        int col = idx & 7;
        const __half* src = g_v + ((size_t)(b * CC + c0 + row)) * NSEQ + j0 + col * 8;
        cp16(tb + SV + row * KROW + col * 16, src);
    }
}

__global__ __launch_bounds__(512, 1) void out_kernel(float* __restrict__ out)
{
    extern __shared__ char smem[];
    const uint32_t sb = smem_u32(smem);
    const int b  = blockIdx.z;
    const int i0 = blockIdx.x * 128;
    const int c0 = blockIdx.y * 256;
    const int t  = threadIdx.x;
    const int w  = t >> 5;
    const int lane = t & 31;
    const int g  = lane >> 2;
    const int t4 = lane & 3;
    const int l8 = lane & 7;
    const int tt = lane >> 3;
    const int ia = w & 7;         // phase A: i-group
    const int jh = w >> 3;        // phase A: j-half
    const int cbw = w & 3;        // phase B: c-group
    const int ib  = w >> 2;       // phase B: i-group

    // stage Q hi/lo [128 i][64 d] into SMEM via cp.async
#pragma unroll
    for (int r = 0; r < 4; r++) {
        int idx = t + r * 512;
        int arr = idx >> 10;
        int row = (idx >> 3) & 127;
        int col = idx & 7;
        const __half* src = (arr ? g_ql : g_qh) + ((size_t)b * NSEQ + i0 + row) * DQK + col * 8;
        cp16(sb + S_Q + arr * 18432 + row * KROW + col * 16, src);
    }
    issue_tiles(sb + S_BUF, b, 0, c0, t);
    CP_COMMIT();

    const uint32_t qlrow = sb + S_Q
        + (uint32_t)(ia * 16 + l8 + ((lane >> 3) & 1) * 8) * KROW
        + (uint32_t)((lane >> 4) * 16);

    float o[2][8][4];
#pragma unroll
    for (int mt = 0; mt < 2; mt++)
#pragma unroll
        for (int nt = 0; nt < 8; nt++)
#pragma unroll
            for (int r = 0; r < 4; r++) o[mt][nt][r] = 0.f;
    float m[2][2]  = {{-1e30f, -1e30f}, {-1e30f, -1e30f}};
    float ls[2][2] = {{0.f, 0.f}, {0.f, 0.f}};

    for (int it = 0; it < N_CHUNK; ++it) {
        if (it + 1 < N_CHUNK)
            issue_tiles(sb + S_BUF + ((it + 1) & 1) * TILE_BYTES, b, (it + 1) * 64, c0, t);
        CP_COMMIT();
        CP_WAIT1();
        __syncthreads();    // tile data ready; prev phase B fully done

        const uint32_t tb = sb + S_BUF + (it & 1) * TILE_BYTES;

        // ================= PHASE A: S = Q K^T (split-3 fp16) ===============
        {
            float s[4][4];
#pragma unroll
            for (int nt = 0; nt < 4; nt++)
#pragma unroll
                for (int r = 0; r < 4; r++) s[nt][r] = 0.f;

#pragma unroll
            for (int kp = 0; kp < 2; kp++) {
                uint32_t qA[4], qB[4], qC[4], qD[4];
                ldsm4(qA, qlrow + kp * 64);
                ldsm4(qB, qlrow + kp * 64 + 32);
                ldsm4(qC, qlrow + 18432 + kp * 64);
                ldsm4(qD, qlrow + 18432 + kp * 64 + 32);
#pragma unroll
                for (int nt = 0; nt < 4; nt++) {
                    uint32_t krow = tb + (jh * 32 + nt * 8 + l8) * KROW + tt * 16;
                    uint32_t kh[4], kl[4];
                    ldsm4(kh, krow + SK_H + kp * 64);
                    ldsm4(kl, krow + SK_L + kp * 64);
                    mma_f16(s[nt], qA, kh[0], kh[1]);
                    mma_f16(s[nt], qB, kh[2], kh[3]);
                    mma_f16(s[nt], qC, kh[0], kh[1]);
                    mma_f16(s[nt], qD, kh[2], kh[3]);
                    mma_f16(s[nt], qA, kl[0], kl[1]);
                    mma_f16(s[nt], qB, kl[2], kl[3]);
                }
            }

            // per-row chunk max over this warp's 32 j
            float cm0 = -1e30f, cm1 = -1e30f;
#pragma unroll
            for (int nt = 0; nt < 4; nt++) {
                cm0 = fmaxf(cm0, fmaxf(s[nt][0], s[nt][1]));
                cm1 = fmaxf(cm1, fmaxf(s[nt][2], s[nt][3]));
            }
            cm0 = fmaxf(cm0, __shfl_xor_sync(0xFFFFFFFFu, cm0, 1));
            cm0 = fmaxf(cm0, __shfl_xor_sync(0xFFFFFFFFu, cm0, 2));
            cm1 = fmaxf(cm1, __shfl_xor_sync(0xFFFFFFFFu, cm1, 1));
            cm1 = fmaxf(cm1, __shfl_xor_sync(0xFFFFFFFFu, cm1, 2));
            if (t4 == 0) {
                sts32f(sb + S_CM + (jh * 128 + ia * 16 + g) * 4, cm0);
                sts32f(sb + S_CM + (jh * 128 + ia * 16 + g + 8) * 4, cm1);
            }
            // store raw S (fp32)
#pragma unroll
            for (int nt = 0; nt < 4; nt++) {
                int col = jh * 32 + nt * 8 + 2 * t4;
                uint32_t a0 = sb + S_S + ((ia * 16 + g) * SROW + col) * 4;
                uint32_t a1 = sb + S_S + ((ia * 16 + g + 8) * SROW + col) * 4;
                sts64(a0, s[nt][0], s[nt][1]);
                sts64(a1, s[nt][2], s[nt][3]);
            }
        }
        __syncthreads();    // S + Scm visible

        // ================= PHASE B: softmax + GEMM2 ========================
        uint32_t a[2][4][4];
#pragma unroll
        for (int mt = 0; mt < 2; mt++) {
            const int r0 = ib * 32 + mt * 16 + g;   // local i row
            float cmx0 = fmaxf(lds32f(sb + S_CM + r0 * 4),
                               lds32f(sb + S_CM + (128 + r0) * 4));
            float cmx1 = fmaxf(lds32f(sb + S_CM + (r0 + 8) * 4),
                               lds32f(sb + S_CM + (128 + r0 + 8) * 4));
            float mn0 = fmaxf(m[mt][0], cmx0 * LOG2E);
            float mn1 = fmaxf(m[mt][1], cmx1 * LOG2E);
            float f0 = exp2_fast(m[mt][0] - mn0);
            float f1 = exp2_fast(m[mt][1] - mn1);
            m[mt][0] = mn0; m[mt][1] = mn1;
            ls[mt][0] *= f0; ls[mt][1] *= f1;
            if (__any_sync(0xFFFFFFFFu, fminf(f0, f1) < 1.0f)) {
#pragma unroll
                for (int nt = 0; nt < 8; nt++) {
                    o[mt][nt][0] *= f0; o[mt][nt][1] *= f0;
                    o[mt][nt][2] *= f1; o[mt][nt][3] *= f1;
                }
            }
            const uint32_t sr0 = sb + S_S + (r0 * SROW + 2 * t4) * 4;
            const uint32_t sr1 = sb + S_S + ((r0 + 8) * SROW + 2 * t4) * 4;
#pragma unroll
            for (int kt = 0; kt < 4; kt++) {
                float2 v00 = lds64(sr0 + kt * 64);
                float2 v01 = lds64(sr0 + kt * 64 + 32);
                float2 v10 = lds64(sr1 + kt * 64);
                float2 v11 = lds64(sr1 + kt * 64 + 32);
                float p00 = exp2_fast(fmaf(v00.x, LOG2E, -mn0));
                float p01 = exp2_fast(fmaf(v00.y, LOG2E, -mn0));
                float p02 = exp2_fast(fmaf(v01.x, LOG2E, -mn0));
                float p03 = exp2_fast(fmaf(v01.y, LOG2E, -mn0));
                float p10 = exp2_fast(fmaf(v10.x, LOG2E, -mn1));
                float p11 = exp2_fast(fmaf(v10.y, LOG2E, -mn1));
                float p12 = exp2_fast(fmaf(v11.x, LOG2E, -mn1));
                float p13 = exp2_fast(fmaf(v11.y, LOG2E, -mn1));
                ls[mt][0] += (p00 + p01) + (p02 + p03);
                ls[mt][1] += (p10 + p11) + (p12 + p13);
                a[mt][kt][0] = pack_h2(p00, p01);
                a[mt][kt][1] = pack_h2(p10, p11);
                a[mt][kt][2] = pack_h2(p02, p03);
                a[mt][kt][3] = pack_h2(p12, p13);
            }
        }

        // GEMM2: o += P V^T, warp tile 32i x 64c
#pragma unroll
        for (int nt = 0; nt < 8; nt++) {
            uint32_t vrow = tb + SV + (cbw * 64 + nt * 8 + l8) * KROW + tt * 16;
#pragma unroll
            for (int kg = 0; kg < 2; kg++) {
                uint32_t vv[4];
                ldsm4(vv, vrow + kg * 64);
                mma_f16(o[0][nt], a[0][2 * kg],     vv[0], vv[1]);
                mma_f16(o[0][nt], a[0][2 * kg + 1], vv[2], vv[3]);
                mma_f16(o[1][nt], a[1][2 * kg],     vv[0], vv[1]);
                mma_f16(o[1][nt], a[1][2 * kg + 1], vv[2], vv[3]);
            }
        }
        __syncthreads();    // phase B done before next prefetch/overwrite
    }

    // final row-sum reduce (lanes sharing a row: xor 1, 2)
#pragma unroll
    for (int mt = 0; mt < 2; mt++)
#pragma unroll
        for (int h = 0; h < 2; h++) {
            float v = ls[mt][h];
            v += __shfl_xor_sync(0xFFFFFFFFu, v, 1);
            v += __shfl_xor_sync(0xFFFFFFFFu, v, 2);
            ls[mt][h] = 1.0f / v;
        }

    // epilogue: scale, transpose through SMEM staging, coalesced store
    float* stg = (float*)smem;
#pragma unroll
    for (int mt = 0; mt < 2; mt++)
#pragma unroll
        for (int nt = 0; nt < 8; nt++) {
            int rbase = ib * 32 + mt * 16 + g;
            int cbase = cbw * 64 + nt * 8 + 2 * t4;
            stg[(size_t)cbase * STG_ROW + rbase]           = o[mt][nt][0] * ls[mt][0];
            stg[(size_t)(cbase + 1) * STG_ROW + rbase]     = o[mt][nt][1] * ls[mt][0];
            stg[(size_t)cbase * STG_ROW + rbase + 8]       = o[mt][nt][2] * ls[mt][1];
            stg[(size_t)(cbase + 1) * STG_ROW + rbase + 8] = o[mt][nt][3] * ls[mt][1];
        }
    __syncthreads();
#pragma unroll
    for (int r = 0; r < 16; r++) {
        int fid = t + r * 512;
        int c = fid >> 5, x = fid & 31;
        float4 v = *(const float4*)&stg[(size_t)c * STG_ROW + x * 4];
        *(float4*)(out + ((size_t)(b * CC + c0 + c)) * NSEQ + i0 + x * 4) = v;
    }
}

// ---------------- launch ----------------------------------------------------
extern "C" void kernel_launch(void* const* d_in, const int* in_sizes, int n_in,
                              void* d_out, int out_size)
{
    const float* x  = (const float*)d_in[0];
    const float* wq = (const float*)d_in[1];
    const float* bq = (const float*)d_in[2];
    const float* wk = (const float*)d_in[3];
    const float* bk = (const float*)d_in[4];
    const float* wv = (const float*)d_in[5];
    const float* bv = (const float*)d_in[6];
    float* out = (float*)d_out;

    proj_kernel<<<dim3(NSEQ / 64, 640 / 64, BB), 256>>>(x, wq, bq, wk, bk, wv, bv);
    cudaFuncSetAttribute(out_kernel, cudaFuncAttributeMaxDynamicSharedMemorySize, OUT_SMEM_BYTES);
    out_kernel<<<dim3(NSEQ / 128, CC / 256, BB), 512, OUT_SMEM_BYTES>>>(out);
}

// round 8
// speedup vs baseline: 1.0869x; 1.0869x over previous
#include <cuda_runtime.h>
#include <cuda_fp16.h>
#include <cstdint>

#define BB   4
#define CC   512
#define NSEQ 4096
#define DQK  64
#define LOG2E 1.4426950408889634f

// ---------------- scratch (static device globals: allocation-free) ----------
__device__ __half g_qh[BB * NSEQ * DQK];            // [b][i][d] hi
__device__ __half g_ql[BB * NSEQ * DQK];            // [b][i][d] lo
__device__ __half g_kh[BB * NSEQ * DQK];            // [b][j][d] hi
__device__ __half g_kl[BB * NSEQ * DQK];            // [b][j][d] lo
__device__ __half g_v [(size_t)BB * CC * NSEQ];     // [b][c][j] single fp16
__device__ __half g_xth[(size_t)BB * NSEQ * CC];    // x^T hi: [b][n][c]
__device__ __half g_xtl[(size_t)BB * NSEQ * CC];    // x^T lo
__device__ __half g_wh[640 * 512];                  // unified W hi: rows q|k|v
__device__ __half g_wl[640 * 512];                  // unified W lo

// ---------------- fast exp2 --------------------------------------------------
__device__ __forceinline__ float exp2_fast(float y) {
    y = fmaxf(y, -120.0f);
    float t = y + 12582912.0f;
    float n = t - 12582912.0f;
    float f = y - n;
    float p = 1.3333558e-3f;
    p = fmaf(p, f, 9.6181291e-3f);
    p = fmaf(p, f, 5.5504109e-2f);
    p = fmaf(p, f, 2.4022651e-1f);
    p = fmaf(p, f, 6.9314718e-1f);
    p = fmaf(p, f, 1.0f);
    int ni = (int)n;
    return __int_as_float(__float_as_int(p) + (ni << 23));
}

__device__ __forceinline__ uint32_t smem_u32(const void* p) {
    uint32_t a;
    asm("{ .reg .u64 t; cvta.to.shared.u64 t, %1; cvt.u32.u64 %0, t; }" : "=r"(a) : "l"(p));
    return a;
}
__device__ __forceinline__ uint32_t pack_h2(float a, float b) {
    __half2 h = __floats2half2_rn(a, b);
    return *(uint32_t*)&h;
}
__device__ __forceinline__ void mma_f16(float* c, const uint32_t* a, uint32_t b0, uint32_t b1) {
    asm volatile("mma.sync.aligned.m16n8k16.row.col.f32.f16.f16.f32 "
        "{%0,%1,%2,%3}, {%4,%5,%6,%7}, {%8,%9}, {%0,%1,%2,%3};"
        : "+f"(c[0]), "+f"(c[1]), "+f"(c[2]), "+f"(c[3])
        : "r"(a[0]), "r"(a[1]), "r"(a[2]), "r"(a[3]), "r"(b0), "r"(b1));
}
__device__ __forceinline__ void ldsm4(uint32_t* r, uint32_t a) {
    asm volatile("ldmatrix.sync.aligned.m8n8.x4.shared.b16 {%0,%1,%2,%3}, [%4];"
        : "=r"(r[0]), "=r"(r[1]), "=r"(r[2]), "=r"(r[3]) : "r"(a));
}
__device__ __forceinline__ void cp16(uint32_t dst, const void* src) {
    asm volatile("cp.async.cg.shared.global [%0], [%1], 16;" :: "r"(dst), "l"(src));
}
#define CP_COMMIT() asm volatile("cp.async.commit_group;" ::: "memory")
#define CP_WAIT1()  asm volatile("cp.async.wait_group 1;" ::: "memory")

// ---------------- conversion kernels ----------------------------------------
__global__ __launch_bounds__(256) void conv_x_kernel(const float* __restrict__ x)
{
    __shared__ float xs[32][65];
    const int b  = blockIdx.z;
    const int c0 = blockIdx.y * 32;
    const int n0 = blockIdx.x * 64;
    const int t  = threadIdx.x;
#pragma unroll
    for (int r = 0; r < 8; r++) {
        int idx = t + r * 256;
        int c = idx >> 6, n = idx & 63;
        xs[c][n] = x[((size_t)(b * CC + c0 + c)) * NSEQ + n0 + n];
    }
    __syncthreads();
#pragma unroll
    for (int r = 0; r < 8; r++) {
        int idx = t + r * 256;
        int n = idx >> 5, c = idx & 31;
        float v = xs[c][n];
        __half h = __float2half_rn(v);
        __half l = __float2half_rn(v - __half2float(h));
        size_t o = ((size_t)(b * NSEQ + n0 + n)) * CC + c0 + c;
        g_xth[o] = h;
        g_xtl[o] = l;
    }
}

__global__ __launch_bounds__(256) void conv_w_kernel(
    const float* __restrict__ wq, const float* __restrict__ wk, const float* __restrict__ wv)
{
#pragma unroll
    for (int e = 0; e < 4; e++) {
        int idx = blockIdx.x * 1024 + e * 256 + threadIdx.x;
        int o = idx >> 9, c = idx & 511;
        float v;
        if (o < 64)       v = wq[o * 512 + c];
        else if (o < 128) v = wk[(o - 64) * 512 + c];
        else              v = wv[(size_t)(o - 128) * 512 + c];
        __half h = __float2half_rn(v);
        __half l = __float2half_rn(v - __half2float(h));
        g_wh[idx] = h;
        g_wl[idx] = l;
    }
}

// ---------------- pass 1: HMMA QKV projection -------------------------------
// CTA: 64 o x 128 n, 8 warps (og=w&3: 16 o rows; nh=w>>2: 64 n). K=512 in
// 8 chunks of 64, double-buffered cp.async. Split-3 fp16 (Ah*Bh+Al*Bh+Ah*Bl).
#define PJ_AH 0
#define PJ_AL 9216
#define PJ_XH 18432
#define PJ_XL 36864
#define PJ_TILE 55296
#define PJ_SMEM (2 * PJ_TILE)

__device__ __forceinline__ void proj_stage(uint32_t tb, int b, int ot, int n0, int cc, int t)
{
#pragma unroll
    for (int r = 0; r < 4; r++) {           // W hi+lo: 1024 16B chunks
        int idx = t + r * 256;
        int arr = idx >> 9;
        int row = (idx >> 3) & 63;
        int col = idx & 7;
        const __half* src = (arr ? g_wl : g_wh) + (size_t)(ot * 64 + row) * 512 + cc * 64 + col * 8;
        cp16(tb + PJ_AH + arr * 9216 + row * 144 + col * 16, src);
    }
#pragma unroll
    for (int r = 0; r < 8; r++) {           // x^T hi+lo: 2048 16B chunks
        int idx = t + r * 256;
        int arr = idx >> 10;
        int row = (idx >> 3) & 127;
        int col = idx & 7;
        const __half* src = (arr ? g_xtl : g_xth) + ((size_t)(b * NSEQ) + n0 + row) * 512 + cc * 64 + col * 8;
        cp16(tb + PJ_XH + arr * 18432 + row * 144 + col * 16, src);
    }
}

__global__ __launch_bounds__(256, 1) void proj_hmma(
    const float* __restrict__ bq, const float* __restrict__ bk, const float* __restrict__ bv)
{
    extern __shared__ char smem[];
    const uint32_t sb = smem_u32(smem);
    const int b  = blockIdx.z;
    const int ot = blockIdx.y;          // o-block: 0=q, 1=k, 2..9=v
    const int n0 = blockIdx.x * 128;
    const int t  = threadIdx.x;
    const int w  = t >> 5;
    const int lane = t & 31;
    const int g  = lane >> 2;
    const int t4 = lane & 3;
    const int l8 = lane & 7;
    const int tt = lane >> 3;
    const int og = w & 3;
    const int nh = w >> 2;

    proj_stage(sb, b, ot, n0, 0, t);
    CP_COMMIT();

    float o[8][4];
#pragma unroll
    for (int nt = 0; nt < 8; nt++)
#pragma unroll
        for (int r = 0; r < 4; r++) o[nt][r] = 0.f;

    for (int cc = 0; cc < 8; ++cc) {
        if (cc + 1 < 8)
            proj_stage(sb + ((cc + 1) & 1) * PJ_TILE, b, ot, n0, cc + 1, t);
        CP_COMMIT();
        CP_WAIT1();
        __syncthreads();

        const uint32_t tb = sb + (cc & 1) * PJ_TILE;
        const uint32_t arow = tb + PJ_AH
            + (uint32_t)(og * 16 + l8 + ((lane >> 3) & 1) * 8) * 144
            + (uint32_t)((lane >> 4) * 16);
#pragma unroll
        for (int kp = 0; kp < 2; kp++) {
            uint32_t ah0[4], ah1[4], al0[4], al1[4];
            ldsm4(ah0, arow + kp * 64);
            ldsm4(ah1, arow + kp * 64 + 32);
            ldsm4(al0, arow + 9216 + kp * 64);
            ldsm4(al1, arow + 9216 + kp * 64 + 32);
#pragma unroll
            for (int nt = 0; nt < 8; nt++) {
                uint32_t xrow = tb + PJ_XH + (nh * 64 + nt * 8 + l8) * 144 + tt * 16 + kp * 64;
                uint32_t bh[4], bl[4];
                ldsm4(bh, xrow);
                ldsm4(bl, xrow + 18432);
                mma_f16(o[nt], ah0, bh[0], bh[1]);
                mma_f16(o[nt], ah1, bh[2], bh[3]);
                mma_f16(o[nt], al0, bh[0], bh[1]);
                mma_f16(o[nt], al1, bh[2], bh[3]);
                mma_f16(o[nt], ah0, bl[0], bl[1]);
                mma_f16(o[nt], ah1, bl[2], bl[3]);
            }
        }
        __syncthreads();
    }

    // epilogue
    const int oglob = ot * 64 + og * 16 + g;
    float b0, b1;
    if (ot == 0)      { b0 = bq[oglob];       b1 = bq[oglob + 8]; }
    else if (ot == 1) { b0 = bk[oglob - 64];  b1 = bk[oglob - 56]; }
    else              { b0 = bv[oglob - 128]; b1 = bv[oglob - 120]; }

    if (ot >= 2) {
        // V block: direct packed fp16 stores to g_v[b][c][n]
        const int cr = oglob - 128;
#pragma unroll
        for (int nt = 0; nt < 8; nt++) {
            size_t base = ((size_t)(b * CC) + cr) * NSEQ + n0 + nh * 64 + nt * 8 + 2 * t4;
            *(uint32_t*)&g_v[base] = pack_h2(o[nt][0] + b0, o[nt][1] + b0);
            *(uint32_t*)&g_v[base + (size_t)8 * NSEQ] = pack_h2(o[nt][2] + b1, o[nt][3] + b1);
        }
    } else {
        // Q/K block: transpose to [n][d] hi/lo via smem (pitch 129 floats)
        __syncthreads();
        float* stg = (float*)smem;
        const int d = og * 16 + g;
#pragma unroll
        for (int nt = 0; nt < 8; nt++) {
            int n = nh * 64 + nt * 8 + 2 * t4;
            stg[d * 129 + n]           = o[nt][0] + b0;
            stg[d * 129 + n + 1]       = o[nt][1] + b0;
            stg[(d + 8) * 129 + n]     = o[nt][2] + b1;
            stg[(d + 8) * 129 + n + 1] = o[nt][3] + b1;
        }
        __syncthreads();
        __half* dsth = (ot == 0) ? g_qh : g_kh;
        __half* dstl = (ot == 0) ? g_ql : g_kl;
#pragma unroll
        for (int it = 0; it < 4; it++) {
            int idx = t + it * 256;
            int row = idx >> 3, d8 = idx & 7;
            __half hh[8], ll[8];
#pragma unroll
            for (int dd = 0; dd < 8; dd++) {
                float v = stg[(d8 * 8 + dd) * 129 + row];
                hh[dd] = __float2half_rn(v);
                ll[dd] = __float2half_rn(v - __half2float(hh[dd]));
            }
            size_t base = ((size_t)(b * NSEQ) + n0 + row) * DQK + d8 * 8;
            *(uint4*)&dsth[base] = *(uint4*)hh;
            *(uint4*)&dstl[base] = *(uint4*)ll;
        }
    }
}

// ---------------- pass 2: HMMA fp16 flash attention (online rescale) ---------
// block 128 i x 256 c, 8 warps (warp = 16 i rows, all 256 c), j in 64-chunks,
// double-buffered cp.async K/V tiles, Q resident in SMEM (ldmatrix per chunk).
#define KROW   144
#define S_QHI  0
#define S_QLO  18432
#define S_BUF  36864
#define SK_H   0
#define SK_L   9216
#define SV     18432
#define TILE_BYTES 55296
#define N_CHUNK (NSEQ / 64)
#define CTILE  256
#define STG_ROW 132
#define OUT_SMEM_BYTES (S_BUF + 2 * TILE_BYTES)

__device__ __forceinline__ void issue_tiles(uint32_t tb, int b, int j0, int c0, int t)
{
#pragma unroll
    for (int r = 0; r < 4; r++) {           // K hi+lo: 1024 16B chunks
        int idx = t + r * 256;
        int arr = idx >> 9;
        int row = (idx >> 3) & 63;
        int col = idx & 7;
        const __half* src = (arr ? g_kl : g_kh) + ((size_t)b * NSEQ + j0 + row) * DQK + col * 8;
        cp16(tb + SK_H + arr * 9216 + row * KROW + col * 16, src);
    }
#pragma unroll
    for (int r = 0; r < 8; r++) {           // V: 2048 16B chunks (256 c rows)
        int idx = t + r * 256;
        int row = (idx >> 3) & 255;
        int col = idx & 7;
        const __half* src = g_v + ((size_t)(b * CC + c0 + row)) * NSEQ + j0 + col * 8;
        cp16(tb + SV + row * KROW + col * 16, src);
    }
}

__global__ __launch_bounds__(256, 1) void out_kernel(float* __restrict__ out)
{
    extern __shared__ char smem[];
    const uint32_t sb = smem_u32(smem);
    const int b  = blockIdx.z;
    const int i0 = blockIdx.x * 128;
    const int c0 = blockIdx.y * CTILE;
    const int t  = threadIdx.x;
    const int w  = t >> 5;
    const int lane = t & 31;
    const int g  = lane >> 2;
    const int t4 = lane & 3;
    const int l8 = lane & 7;
    const int tt = lane >> 3;

    const uint32_t qlrow = (uint32_t)(w * 16 + l8 + ((lane >> 3) & 1) * 8) * KROW
                         + (uint32_t)((lane >> 4) * 16);

#pragma unroll
    for (int r = 0; r < 8; r++) {
        int idx = t + r * 256;
        int arr = idx >> 10;
        int row = (idx >> 3) & 127;
        int col = idx & 7;
        const __half* src = (arr ? g_ql : g_qh) + ((size_t)b * NSEQ + i0 + row) * DQK + col * 8;
        cp16(sb + S_QHI + arr * 18432 + row * KROW + col * 16, src);
    }
    issue_tiles(sb + S_BUF, b, 0, c0, t);
    CP_COMMIT();

    float o[CTILE / 8][4];
#pragma unroll
    for (int ct = 0; ct < CTILE / 8; ct++)
#pragma unroll
        for (int r = 0; r < 4; r++) o[ct][r] = 0.f;
    float m0 = -1e30f, m1 = -1e30f;
    float lsum0 = 0.f, lsum1 = 0.f;

    for (int it = 0; it < N_CHUNK; ++it) {
        if (it + 1 < N_CHUNK)
            issue_tiles(sb + S_BUF + ((it + 1) & 1) * TILE_BYTES, b, (it + 1) * 64, c0, t);
        CP_COMMIT();
        CP_WAIT1();
        __syncthreads();

        const uint32_t tb = sb + S_BUF + (it & 1) * TILE_BYTES;

        // ---- GEMM1: S = Q K^T (fp16 split-3), Q from SMEM ----
        float s[8][4];
#pragma unroll
        for (int nt = 0; nt < 8; nt++)
#pragma unroll
            for (int r = 0; r < 4; r++) s[nt][r] = 0.f;

#pragma unroll
        for (int grp = 0; grp < 2; grp++) {
#pragma unroll
            for (int kp = 0; kp < 2; kp++) {
                uint32_t qh0[4], qh1[4], ql0[4], ql1[4];
                uint32_t qcol = (uint32_t)(kp * 64);
                ldsm4(qh0, sb + S_QHI + qlrow + qcol);
                ldsm4(qh1, sb + S_QHI + qlrow + qcol + 32);
                ldsm4(ql0, sb + S_QLO + qlrow + qcol);
                ldsm4(ql1, sb + S_QLO + qlrow + qcol + 32);
#pragma unroll
                for (int q = 0; q < 4; q++) {
                    int nt = grp * 4 + q;
                    uint32_t krow = tb + (nt * 8 + l8) * KROW + tt * 16;
                    uint32_t kh[4], kl[4];
                    ldsm4(kh, krow + SK_H + kp * 64);
                    ldsm4(kl, krow + SK_L + kp * 64);
                    mma_f16(s[nt], qh0, kh[0], kh[1]);
                    mma_f16(s[nt], qh1, kh[2], kh[3]);
                    mma_f16(s[nt], ql0, kh[0], kh[1]);
                    mma_f16(s[nt], ql1, kh[2], kh[3]);
                    mma_f16(s[nt], qh0, kl[0], kl[1]);
                    mma_f16(s[nt], qh1, kl[2], kl[3]);
                }
            }
        }

        // ---- online rescale ----
        float cm0 = -1e30f, cm1 = -1e30f;
#pragma unroll
        for (int nt = 0; nt < 8; nt++) {
            cm0 = fmaxf(cm0, fmaxf(s[nt][0], s[nt][1]));
            cm1 = fmaxf(cm1, fmaxf(s[nt][2], s[nt][3]));
        }
        cm0 = fmaxf(cm0, __shfl_xor_sync(0xFFFFFFFFu, cm0, 1));
        cm0 = fmaxf(cm0, __shfl_xor_sync(0xFFFFFFFFu, cm0, 2));
        cm1 = fmaxf(cm1, __shfl_xor_sync(0xFFFFFFFFu, cm1, 1));
        cm1 = fmaxf(cm1, __shfl_xor_sync(0xFFFFFFFFu, cm1, 2));
        float m0n = fmaxf(m0, cm0 * LOG2E);
        float m1n = fmaxf(m1, cm1 * LOG2E);
        float f0 = exp2_fast(m0 - m0n);
        float f1 = exp2_fast(m1 - m1n);
        m0 = m0n; m1 = m1n;
        lsum0 *= f0; lsum1 *= f1;
        if (__any_sync(0xFFFFFFFFu, fminf(f0, f1) < 0.9999995f)) {
#pragma unroll
            for (int ct = 0; ct < CTILE / 8; ct++) {
                o[ct][0] *= f0; o[ct][1] *= f0;
                o[ct][2] *= f1; o[ct][3] *= f1;
            }
        }

        // ---- softmax exp + pack P ----
        uint32_t pa[4][4];
#pragma unroll
        for (int kt4 = 0; kt4 < 4; kt4++)
#pragma unroll
            for (int h = 0; h < 2; h++) {
                int nt = kt4 * 2 + h;
                float p0 = exp2_fast(fmaf(s[nt][0], LOG2E, -m0));
                float p1 = exp2_fast(fmaf(s[nt][1], LOG2E, -m0));
                float p2 = exp2_fast(fmaf(s[nt][2], LOG2E, -m1));
                float p3 = exp2_fast(fmaf(s[nt][3], LOG2E, -m1));
                lsum0 += p0 + p1;
                lsum1 += p2 + p3;
                pa[kt4][2 * h + 0] = pack_h2(p0, p1);
                pa[kt4][2 * h + 1] = pack_h2(p2, p3);
            }

        // ---- GEMM2: O += P V^T ----
#pragma unroll
        for (int ct = 0; ct < CTILE / 8; ct++) {
            uint32_t vrow = tb + SV + (ct * 8 + l8) * KROW + tt * 16;
#pragma unroll
            for (int jh = 0; jh < 2; jh++) {
                uint32_t vv[4];
                ldsm4(vv, vrow + jh * 64);
                mma_f16(o[ct], pa[2 * jh],     vv[0], vv[1]);
                mma_f16(o[ct], pa[2 * jh + 1], vv[2], vv[3]);
            }
        }
        __syncthreads();
    }

    lsum0 += __shfl_xor_sync(0xFFFFFFFFu, lsum0, 1);
    lsum0 += __shfl_xor_sync(0xFFFFFFFFu, lsum0, 2);
    lsum1 += __shfl_xor_sync(0xFFFFFFFFu, lsum1, 1);
    lsum1 += __shfl_xor_sync(0xFFFFFFFFu, lsum1, 2);
    const float li0 = 1.0f / lsum0;
    const float li1 = 1.0f / lsum1;

    float* stg = (float*)smem;
    const int il = w * 16 + g;
#pragma unroll
    for (int ct = 0; ct < CTILE / 8; ct++) {
        int c = ct * 8 + 2 * t4;
        stg[(size_t)c * STG_ROW + il]           = o[ct][0] * li0;
        stg[(size_t)(c + 1) * STG_ROW + il]     = o[ct][1] * li0;
        stg[(size_t)c * STG_ROW + il + 8]       = o[ct][2] * li1;
        stg[(size_t)(c + 1) * STG_ROW + il + 8] = o[ct][3] * li1;
    }
    __syncthreads();
#pragma unroll
    for (int r = 0; r < CTILE / 8; r++) {
        int fid = t + r * 256;
        int c = fid >> 5, x = fid & 31;
        float4 v = *(const float4*)&stg[(size_t)c * STG_ROW + x * 4];
        *(float4*)(out + ((size_t)(b * CC + c0 + c)) * NSEQ + i0 + x * 4) = v;
    }
}

// ---------------- launch ----------------------------------------------------
extern "C" void kernel_launch(void* const* d_in, const int* in_sizes, int n_in,
                              void* d_out, int out_size)
{
    const float* x  = (const float*)d_in[0];
    const float* wq = (const float*)d_in[1];
    const float* bq = (const float*)d_in[2];
    const float* wk = (const float*)d_in[3];
    const float* bk = (const float*)d_in[4];
    const float* wv = (const float*)d_in[5];
    const float* bv = (const float*)d_in[6];
    float* out = (float*)d_out;

    conv_x_kernel<<<dim3(NSEQ / 64, CC / 32, BB), 256>>>(x);
    conv_w_kernel<<<320, 256>>>(wq, wk, wv);
    cudaFuncSetAttribute(proj_hmma, cudaFuncAttributeMaxDynamicSharedMemorySize, PJ_SMEM);
    proj_hmma<<<dim3(NSEQ / 128, 10, BB), 256, PJ_SMEM>>>(bq, bk, bv);
    cudaFuncSetAttribute(out_kernel, cudaFuncAttributeMaxDynamicSharedMemorySize, OUT_SMEM_BYTES);
    out_kernel<<<dim3(NSEQ / 128, CC / CTILE, BB), 256, OUT_SMEM_BYTES>>>(out);
}

// round 9
// speedup vs baseline: 1.4122x; 1.2993x over previous
#include <cuda_runtime.h>
#include <cuda_fp16.h>
#include <cstdint>

#define BB   4
#define CC   512
#define NSEQ 4096
#define DQK  64
#define LOG2E 1.4426950408889634f

// ---------------- scratch (static device globals: allocation-free) ----------
__device__ __half g_qh[BB * NSEQ * DQK];            // [b][i][d] hi
__device__ __half g_ql[BB * NSEQ * DQK];            // [b][i][d] lo
__device__ __half g_kh[BB * NSEQ * DQK];            // [b][j][d] hi
__device__ __half g_kl[BB * NSEQ * DQK];            // [b][j][d] lo
__device__ __half g_v [(size_t)BB * CC * NSEQ];     // [b][c][j] single fp16

__device__ __forceinline__ float ex2f(float x) {
    float r; asm("ex2.approx.f32 %0, %1;" : "=f"(r) : "f"(x)); return r;
}
__device__ __forceinline__ uint32_t smem_u32(const void* p) {
    uint32_t a;
    asm("{ .reg .u64 t; cvta.to.shared.u64 t, %1; cvt.u32.u64 %0, t; }" : "=r"(a) : "l"(p));
    return a;
}
__device__ __forceinline__ uint32_t pack_h2(float a, float b) {
    __half2 h = __floats2half2_rn(a, b);
    return *(uint32_t*)&h;
}
__device__ __forceinline__ void mma_f16(float* c, const uint32_t* a, uint32_t b0, uint32_t b1) {
    asm volatile("mma.sync.aligned.m16n8k16.row.col.f32.f16.f16.f32 "
        "{%0,%1,%2,%3}, {%4,%5,%6,%7}, {%8,%9}, {%0,%1,%2,%3};"
        : "+f"(c[0]), "+f"(c[1]), "+f"(c[2]), "+f"(c[3])
        : "r"(a[0]), "r"(a[1]), "r"(a[2]), "r"(a[3]), "r"(b0), "r"(b1));
}
__device__ __forceinline__ void ldsm4(uint32_t* r, uint32_t a) {
    asm volatile("ldmatrix.sync.aligned.m8n8.x4.shared.b16 {%0,%1,%2,%3}, [%4];"
        : "=r"(r[0]), "=r"(r[1]), "=r"(r[2]), "=r"(r[3]) : "r"(a));
}
__device__ __forceinline__ void cp16(uint32_t dst, const void* src) {
    asm volatile("cp.async.cg.shared.global [%0], [%1], 16;" :: "r"(dst), "l"(src));
}
#define CP_COMMIT() asm volatile("cp.async.commit_group;" ::: "memory")
#define CP_WAIT1()  asm volatile("cp.async.wait_group 1;" ::: "memory")

// ---------------- pass 1: QKV projection (SIMT fp32) ------------------------
__global__ __launch_bounds__(256) void proj_kernel(
    const float* __restrict__ x,
    const float* __restrict__ wq, const float* __restrict__ bq,
    const float* __restrict__ wk, const float* __restrict__ bk,
    const float* __restrict__ wv, const float* __restrict__ bv)
{
    __shared__ float ws[16][68];
    __shared__ float xs[16][64];

    const int b  = blockIdx.z;
    const int o0 = blockIdx.y * 64;
    const int n0 = blockIdx.x * 64;
    const int t  = threadIdx.x;
    const int tx = t & 15;
    const int ty = t >> 4;
    const float* xb = x + (size_t)b * CC * NSEQ;

    float acc[4][4];
#pragma unroll
    for (int i = 0; i < 4; i++)
#pragma unroll
        for (int j = 0; j < 4; j++) acc[i][j] = 0.f;

    const int wo  = t >> 2;
    const int wc4 = (t & 3) * 4;
    const int oo  = o0 + wo;
    const float* wrow;
    if (oo < 64)        wrow = wq + (size_t)oo * CC;
    else if (oo < 128)  wrow = wk + (size_t)(oo - 64) * CC;
    else                wrow = wv + (size_t)(oo - 128) * CC;

    const int xc  = t >> 4;
    const int xn4 = (t & 15) * 4;

    for (int c0 = 0; c0 < CC; c0 += 16) {
        float4 w4 = *(const float4*)(wrow + c0 + wc4);
        float4 x4 = *(const float4*)(xb + (size_t)(c0 + xc) * NSEQ + n0 + xn4);
        __syncthreads();
        ws[wc4 + 0][wo] = w4.x; ws[wc4 + 1][wo] = w4.y;
        ws[wc4 + 2][wo] = w4.z; ws[wc4 + 3][wo] = w4.w;
        *(float4*)&xs[xc][xn4] = x4;
        __syncthreads();
#pragma unroll
        for (int c = 0; c < 16; c++) {
            float4 a4 = *(const float4*)&ws[c][4 * ty];
            float4 b4 = *(const float4*)&xs[c][4 * tx];
            float a[4] = {a4.x, a4.y, a4.z, a4.w};
            float bv2[4] = {b4.x, b4.y, b4.z, b4.w};
#pragma unroll
            for (int i = 0; i < 4; i++)
#pragma unroll
                for (int j = 0; j < 4; j++)
                    acc[i][j] = fmaf(a[i], bv2[j], acc[i][j]);
        }
    }

    const int n = n0 + 4 * tx;
#pragma unroll
    for (int mi = 0; mi < 4; mi++) {
        int o = o0 + 4 * ty + mi;
        if (o < 128) {
            int d = o & 63;
            float bias = (o < 64) ? bq[d] : bk[d];
            __half* dh = ((o < 64) ? g_qh : g_kh) + ((size_t)b * NSEQ + n) * DQK + d;
            __half* dl = ((o < 64) ? g_ql : g_kl) + ((size_t)b * NSEQ + n) * DQK + d;
            float vs[4] = {acc[mi][0] + bias, acc[mi][1] + bias,
                           acc[mi][2] + bias, acc[mi][3] + bias};
#pragma unroll
            for (int j = 0; j < 4; j++) {
                __half h = __float2half_rn(vs[j]);
                __half l = __float2half_rn(vs[j] - __half2float(h));
                dh[(size_t)j * DQK] = h;
                dl[(size_t)j * DQK] = l;
            }
        } else {
            int c = o - 128;
            float bias = bv[c];
            size_t off = ((size_t)(b * CC + c)) * NSEQ + n;
            uint2 w2;
            w2.x = pack_h2(acc[mi][0] + bias, acc[mi][1] + bias);
            w2.y = pack_h2(acc[mi][2] + bias, acc[mi][3] + bias);
            *(uint2*)((char*)g_v + off * 2) = w2;
        }
    }
}

// ---------------- pass 2: HMMA fp16 flash attention (online rescale) ---------
// block 128 i x 256 c, 8 warps (warp = 16 i rows, all 256 c), j in 64-chunks,
// double-buffered cp.async K/V tiles, Q resident in SMEM (ldmatrix per chunk).
// Softmax: MUFU EX2; row sums via ones-vector MMA (fp32 tensor-core exact).
#define KROW   144
#define S_QHI  0
#define S_QLO  18432
#define S_BUF  36864
#define SK_H   0
#define SK_L   9216
#define SV     18432
#define TILE_BYTES 55296
#define N_CHUNK (NSEQ / 64)
#define CTILE  256
#define STG_ROW 132
#define OUT_SMEM_BYTES (S_BUF + 2 * TILE_BYTES)

__device__ __forceinline__ void issue_tiles(uint32_t tb, int b, int j0, int c0, int t)
{
#pragma unroll
    for (int r = 0; r < 4; r++) {           // K hi+lo: 1024 16B chunks
        int idx = t + r * 256;
        int arr = idx >> 9;
        int row = (idx >> 3) & 63;
        int col = idx & 7;
        const __half* src = (arr ? g_kl : g_kh) + ((size_t)b * NSEQ + j0 + row) * DQK + col * 8;
        cp16(tb + SK_H + arr * 9216 + row * KROW + col * 16, src);
    }
#pragma unroll
    for (int r = 0; r < 8; r++) {           // V: 2048 16B chunks (256 c rows)
        int idx = t + r * 256;
        int row = (idx >> 3) & 255;
        int col = idx & 7;
        const __half* src = g_v + ((size_t)(b * CC + c0 + row)) * NSEQ + j0 + col * 8;
        cp16(tb + SV + row * KROW + col * 16, src);
    }
}

__global__ __launch_bounds__(256, 1) void out_kernel(float* __restrict__ out)
{
    extern __shared__ char smem[];
    const uint32_t sb = smem_u32(smem);
    const int b  = blockIdx.z;
    const int i0 = blockIdx.x * 128;
    const int c0 = blockIdx.y * CTILE;
    const int t  = threadIdx.x;
    const int w  = t >> 5;
    const int lane = t & 31;
    const int g  = lane >> 2;
    const int t4 = lane & 3;
    const int l8 = lane & 7;
    const int tt = lane >> 3;

    const uint32_t qlrow = (uint32_t)(w * 16 + l8 + ((lane >> 3) & 1) * 8) * KROW
                         + (uint32_t)((lane >> 4) * 16);

#pragma unroll
    for (int r = 0; r < 8; r++) {
        int idx = t + r * 256;
        int arr = idx >> 10;
        int row = (idx >> 3) & 127;
        int col = idx & 7;
        const __half* src = (arr ? g_ql : g_qh) + ((size_t)b * NSEQ + i0 + row) * DQK + col * 8;
        cp16(sb + S_QHI + arr * 18432 + row * KROW + col * 16, src);
    }
    issue_tiles(sb + S_BUF, b, 0, c0, t);
    CP_COMMIT();

    float o[CTILE / 8][4];
#pragma unroll
    for (int ct = 0; ct < CTILE / 8; ct++)
#pragma unroll
        for (int r = 0; r < 4; r++) o[ct][r] = 0.f;
    float la[4] = {0.f, 0.f, 0.f, 0.f};   // row-sum accumulator (ones-MMA C frag)
    float m0 = -1e30f, m1 = -1e30f;

    const uint32_t ONE2 = 0x3C003C00u;    // half2(1.0, 1.0)

    for (int it = 0; it < N_CHUNK; ++it) {
        if (it + 1 < N_CHUNK)
            issue_tiles(sb + S_BUF + ((it + 1) & 1) * TILE_BYTES, b, (it + 1) * 64, c0, t);
        CP_COMMIT();
        CP_WAIT1();
        __syncthreads();

        const uint32_t tb = sb + S_BUF + (it & 1) * TILE_BYTES;

        // ---- GEMM1: S = Q K^T (fp16 split-3), Q from SMEM ----
        float s[8][4];
#pragma unroll
        for (int nt = 0; nt < 8; nt++)
#pragma unroll
            for (int r = 0; r < 4; r++) s[nt][r] = 0.f;

#pragma unroll
        for (int grp = 0; grp < 2; grp++) {
#pragma unroll
            for (int kp = 0; kp < 2; kp++) {
                uint32_t qh0[4], qh1[4], ql0[4], ql1[4];
                uint32_t qcol = (uint32_t)(kp * 64);
                ldsm4(qh0, sb + S_QHI + qlrow + qcol);
                ldsm4(qh1, sb + S_QHI + qlrow + qcol + 32);
                ldsm4(ql0, sb + S_QLO + qlrow + qcol);
                ldsm4(ql1, sb + S_QLO + qlrow + qcol + 32);
#pragma unroll
                for (int q = 0; q < 4; q++) {
                    int nt = grp * 4 + q;
                    uint32_t krow = tb + (nt * 8 + l8) * KROW + tt * 16;
                    uint32_t kh[4], kl[4];
                    ldsm4(kh, krow + SK_H + kp * 64);
                    ldsm4(kl, krow + SK_L + kp * 64);
                    mma_f16(s[nt], qh0, kh[0], kh[1]);
                    mma_f16(s[nt], qh1, kh[2], kh[3]);
                    mma_f16(s[nt], ql0, kh[0], kh[1]);
                    mma_f16(s[nt], ql1, kh[2], kh[3]);
                    mma_f16(s[nt], qh0, kl[0], kl[1]);
                    mma_f16(s[nt], qh1, kl[2], kl[3]);
                }
            }
        }

        // ---- online rescale: chunk max -> update frame ----
        float cm0 = -1e30f, cm1 = -1e30f;
#pragma unroll
        for (int nt = 0; nt < 8; nt++) {
            cm0 = fmaxf(cm0, fmaxf(s[nt][0], s[nt][1]));
            cm1 = fmaxf(cm1, fmaxf(s[nt][2], s[nt][3]));
        }
        cm0 = fmaxf(cm0, __shfl_xor_sync(0xFFFFFFFFu, cm0, 1));
        cm0 = fmaxf(cm0, __shfl_xor_sync(0xFFFFFFFFu, cm0, 2));
        cm1 = fmaxf(cm1, __shfl_xor_sync(0xFFFFFFFFu, cm1, 1));
        cm1 = fmaxf(cm1, __shfl_xor_sync(0xFFFFFFFFu, cm1, 2));
        float m0n = fmaxf(m0, cm0 * LOG2E);
        float m1n = fmaxf(m1, cm1 * LOG2E);
        float f0 = ex2f(m0 - m0n);
        float f1 = ex2f(m1 - m1n);
        m0 = m0n; m1 = m1n;
        la[0] *= f0; la[1] *= f0; la[2] *= f1; la[3] *= f1;
        if (__any_sync(0xFFFFFFFFu, fminf(f0, f1) < 0.9999995f)) {
#pragma unroll
            for (int ct = 0; ct < CTILE / 8; ct++) {
                o[ct][0] *= f0; o[ct][1] *= f0;
                o[ct][2] *= f1; o[ct][3] *= f1;
            }
        }

        // ---- softmax exp (MUFU EX2) + pack P ----
        uint32_t pa[4][4];
#pragma unroll
        for (int kt4 = 0; kt4 < 4; kt4++)
#pragma unroll
            for (int h = 0; h < 2; h++) {
                int nt = kt4 * 2 + h;
                float p0 = ex2f(fmaf(s[nt][0], LOG2E, -m0));
                float p1 = ex2f(fmaf(s[nt][1], LOG2E, -m0));
                float p2 = ex2f(fmaf(s[nt][2], LOG2E, -m1));
                float p3 = ex2f(fmaf(s[nt][3], LOG2E, -m1));
                pa[kt4][2 * h + 0] = pack_h2(p0, p1);
                pa[kt4][2 * h + 1] = pack_h2(p2, p3);
            }

        // ---- row sums via ones-MMA: la += P . 1 (fp32 exact) ----
#pragma unroll
        for (int kt4 = 0; kt4 < 4; kt4++)
            mma_f16(la, pa[kt4], ONE2, ONE2);

        // ---- GEMM2: O += P V^T ----
#pragma unroll
        for (int ct = 0; ct < CTILE / 8; ct++) {
            uint32_t vrow = tb + SV + (ct * 8 + l8) * KROW + tt * 16;
#pragma unroll
            for (int jh = 0; jh < 2; jh++) {
                uint32_t vv[4];
                ldsm4(vv, vrow + jh * 64);
                mma_f16(o[ct], pa[2 * jh],     vv[0], vv[1]);
                mma_f16(o[ct], pa[2 * jh + 1], vv[2], vv[3]);
            }
        }
        __syncthreads();
    }

    // la holds full row sums (all lanes of a row identical by construction)
    const float li0 = 1.0f / la[0];
    const float li1 = 1.0f / la[2];

    float* stg = (float*)smem;
    const int il = w * 16 + g;
#pragma unroll
    for (int ct = 0; ct < CTILE / 8; ct++) {
        int c = ct * 8 + 2 * t4;
        stg[(size_t)c * STG_ROW + il]           = o[ct][0] * li0;
        stg[(size_t)(c + 1) * STG_ROW + il]     = o[ct][1] * li0;
        stg[(size_t)c * STG_ROW + il + 8]       = o[ct][2] * li1;
        stg[(size_t)(c + 1) * STG_ROW + il + 8] = o[ct][3] * li1;
    }
    __syncthreads();
#pragma unroll
    for (int r = 0; r < CTILE / 8; r++) {
        int fid = t + r * 256;
        int c = fid >> 5, x = fid & 31;
        float4 v = *(const float4*)&stg[(size_t)c * STG_ROW + x * 4];
        *(float4*)(out + ((size_t)(b * CC + c0 + c)) * NSEQ + i0 + x * 4) = v;
    }
}

// ---------------- launch ----------------------------------------------------
extern "C" void kernel_launch(void* const* d_in, const int* in_sizes, int n_in,
                              void* d_out, int out_size)
{
    const float* x  = (const float*)d_in[0];
    const float* wq = (const float*)d_in[1];
    const float* bq = (const float*)d_in[2];
    const float* wk = (const float*)d_in[3];
    const float* bk = (const float*)d_in[4];
    const float* wv = (const float*)d_in[5];
    const float* bv = (const float*)d_in[6];
    float* out = (float*)d_out;

    proj_kernel<<<dim3(NSEQ / 64, 640 / 64, BB), 256>>>(x, wq, bq, wk, bk, wv, bv);
    cudaFuncSetAttribute(out_kernel, cudaFuncAttributeMaxDynamicSharedMemorySize, OUT_SMEM_BYTES);
    out_kernel<<<dim3(NSEQ / 128, CC / CTILE, BB), 256, OUT_SMEM_BYTES>>>(out);
}